// round 16
// baseline (speedup 1.0000x reference)
#include <cuda_runtime.h>
#include <cuda_bf16.h>
#include <cstdint>
#include <cstddef>

#define SEQ_LEN 16384
#define HID 2048
#define EMBD 512
#define NCH 128
#define ZD 2560
#define SMEM_ROWS 56
#define LSTM_SMEM (SMEM_ROWS * 4096 + 128 * 4)            // 229,888 B  (<= 232,448 opt-in)
#define PGEMM_SMEM ((64 + 128) * 129 * 4)                 // 99,072 B
#define NFLAGS 160

typedef unsigned long long ull;

__device__ __nv_bfloat16 g_Wh[(size_t)4 * HID * HID];      // [gate][row][k], k over h-part
__device__ float         g_P[(size_t)NCH * 4 * HID];       // x-part preact + bias
__device__ float         g_H[((size_t)SEQ_LEN + 1) * HID]; // h history
__device__ unsigned int  g_flags[NFLAGS];                  // per-block publish counters

__device__ __forceinline__ float bflo(unsigned int w) { return __uint_as_float(w << 16); }
__device__ __forceinline__ float bfhi(unsigned int w) { return __uint_as_float(w & 0xffff0000u); }
__device__ __forceinline__ float sigmoid_f(float x) { return 1.0f / (1.0f + __expf(-x)); }
__device__ __forceinline__ float tanh_f(float x)    { return 2.0f / (1.0f + __expf(-2.0f * x)) - 1.0f; }

__device__ __forceinline__ ull packf2(float lo, float hi) {
    ull r; asm("mov.b64 %0, {%1, %2};" : "=l"(r) : "f"(lo), "f"(hi)); return r;
}
__device__ __forceinline__ void unpackf2(ull v, float& lo, float& hi) {
    asm("mov.b64 {%0, %1}, %2;" : "=f"(lo), "=f"(hi) : "l"(v));
}
__device__ __forceinline__ void ffma2(ull& d, ull a, ull b) {
    asm("fma.rn.f32x2 %0, %1, %2, %0;" : "+l"(d) : "l"(a), "l"(b));
}
__device__ __forceinline__ unsigned ld_flag_volatile(const unsigned* p) {
    unsigned v; asm volatile("ld.volatile.global.u32 %0, [%1];" : "=r"(v) : "l"(p)); return v;
}
__device__ __forceinline__ void st_flag_release(unsigned* p, unsigned v) {
    asm volatile("st.release.gpu.global.u32 [%0], %1;" :: "l"(p), "r"(v) : "memory");
}

__global__ void init_flags(int nb) {
    int i = threadIdx.x;
    if (i < NFLAGS) g_flags[i] = (i < nb) ? 0u : 0xFFFFFFFFu;
}

// ---- convert recurrent halves of Wf/Wi/Wg/Wo to bf16 ----
__global__ void __launch_bounds__(256) wh_convert(
    const float* __restrict__ Wf, const float* __restrict__ Wi,
    const float* __restrict__ Wg, const float* __restrict__ Wo)
{
    size_t idx = (size_t)blockIdx.x * 256 + threadIdx.x;   // bf16-pair index
    if (idx >= (size_t)4 * HID * HID / 2) return;
    unsigned gate = (unsigned)(idx >> 21);
    unsigned rem  = (unsigned)idx & ((1u << 21) - 1u);
    unsigned row  = rem >> 10;
    unsigned p    = rem & 1023u;
    const float* W = (gate == 0) ? Wf : (gate == 1) ? Wi : (gate == 2) ? Wg : Wo;
    float2 v = *(const float2*)(W + (size_t)row * ZD + EMBD + 2u * p);
    reinterpret_cast<__nv_bfloat162*>(g_Wh)[idx] = __floats2bfloat162_rn(v.x, v.y);
}

// ---- P table: [8192 x 512] @ [512 x 128] exact fp32 ----
__global__ void __launch_bounds__(256) pgemm_kernel(
    const float* __restrict__ Wf, const float* __restrict__ bf,
    const float* __restrict__ Wi, const float* __restrict__ bi,
    const float* __restrict__ Wg, const float* __restrict__ bg,
    const float* __restrict__ Wo, const float* __restrict__ bo,
    const float* __restrict__ emb)
{
    extern __shared__ float psm[];
    float* sW = psm;               // [64][129]
    float* sE = psm + 64 * 129;    // [128][129]
    const int tid = threadIdx.x;
    const int ty = tid >> 4, tx = tid & 15;
    const int gpos0 = blockIdx.x * 64;
    const int gate = gpos0 >> 11;
    const int rowbase = gpos0 & (HID - 1);
    const float* W  = (gate == 0) ? Wf : (gate == 1) ? Wi : (gate == 2) ? Wg : Wo;
    const float* bb = (gate == 0) ? bf : (gate == 1) ? bi : (gate == 2) ? bg : bo;

    float acc[4][8];
#pragma unroll
    for (int i = 0; i < 4; i++)
#pragma unroll
        for (int j = 0; j < 8; j++) acc[i][j] = 0.0f;

    for (int kb = 0; kb < 4; kb++) {
        __syncthreads();
        for (int i = tid; i < 64 * 128; i += 256) {
            int r = i >> 7, k = i & 127;
            sW[r * 129 + k] = W[(size_t)(rowbase + r) * ZD + kb * 128 + k];
        }
        for (int i = tid; i < 128 * 128; i += 256) {
            int c = i >> 7, k = i & 127;
            sE[c * 129 + k] = emb[(size_t)c * EMBD + kb * 128 + k];
        }
        __syncthreads();
        for (int k = 0; k < 128; k++) {
            float wv[4], ev[8];
#pragma unroll
            for (int i = 0; i < 4; i++) wv[i] = sW[(ty + 16 * i) * 129 + k];
#pragma unroll
            for (int j = 0; j < 8; j++) ev[j] = sE[(tx + 16 * j) * 129 + k];
#pragma unroll
            for (int i = 0; i < 4; i++)
#pragma unroll
                for (int j = 0; j < 8; j++) acc[i][j] = fmaf(wv[i], ev[j], acc[i][j]);
        }
    }
#pragma unroll
    for (int i = 0; i < 4; i++) {
        float bv = bb[rowbase + ty + 16 * i];
#pragma unroll
        for (int j = 0; j < 8; j++)
            g_P[(size_t)(tx + 16 * j) * (4 * HID) + gpos0 + ty + 16 * i] = acc[i][j] + bv;
    }
}

// ---- persistent LSTM: flag-array barrier, direct L2 h loads, all rows in SMEM ----
__global__ void __launch_bounds__(512, 1) lstm_persist(
    const int* __restrict__ seq, float* __restrict__ dout)
{
    const int nb = gridDim.x, b = blockIdx.x;
    const int qq = HID / nb, rm = HID % nb;
    const int R = qq + (b < rm ? 1 : 0);
    const int rbase = b * qq + (b < rm ? b : rm);
    const int nGR = 4 * R;                                   // <= 56 == SMEM_ROWS
    const int tid = threadIdx.x, warp = tid >> 5, lane = tid & 31;
    const int khalf = warp & 1;        // 1024-wide half of the dot
    const int wslot = warp >> 1;       // 0..7 : row slot
    const int nrows = (nGR > wslot) ? ((nGR - wslot + 7) >> 3) : 0;  // 6 or 7

    extern __shared__ unsigned char smraw[];
    uint4* wsm  = (uint4*)smraw;                                   // [SMEM_ROWS][256]
    float* gacc = (float*)(smraw + SMEM_ROWS * 4096);              // [56][2] partials

    // prologue: all weight rows into SMEM
    for (int gr = 0; gr < nGR; gr++) {
        int gate = gr & 3, row = rbase + (gr >> 2);
        const uint4* src = (const uint4*)(g_Wh + ((size_t)gate * HID + row) * HID);
        if (tid < 256) wsm[gr * 256 + tid] = __ldg(src + tid);
    }
    float cst = 0.0f;

    // publish h_0 = 0 for this block's slice
    if (warp == 0) {
        if (lane < R) g_H[rbase + lane] = 0.0f;
        __syncwarp();
        if (lane == 0) st_flag_release(&g_flags[b], 1u);
    }
    __syncthreads();

    for (int t = 0; t < SEQ_LEN; t++) {
        // warp 1: poll all flags >= t+1 (parallel, contention-free reads)
        if (warp == 1) {
            const unsigned tgt = (unsigned)(t + 1);
            unsigned ok;
            do {
                unsigned m0 = ld_flag_volatile(&g_flags[lane]);
                unsigned m1 = ld_flag_volatile(&g_flags[lane + 32]);
                unsigned m2 = ld_flag_volatile(&g_flags[lane + 64]);
                unsigned m3 = ld_flag_volatile(&g_flags[lane + 96]);
                unsigned m4 = ld_flag_volatile(&g_flags[lane + 128]);
                unsigned m = min(min(min(m0, m1), min(m2, m3)), m4);
                ok = (m >= tgt) ? 1u : 0u;
            } while (__ballot_sync(0xffffffffu, ok) != 0xffffffffu);
            asm volatile("fence.acq_rel.gpu;" ::: "memory");
        }
        // warp 0: prefetch x-part preactivations (independent of h_t)
        float pf = 0.f, pi = 0.f, pg = 0.f, po = 0.f;
        if (warp == 0 && lane < R) {
            int ch = __ldg(seq + t);
            const float* Pr = g_P + (size_t)ch * (4 * HID) + rbase + lane;
            pf = __ldg(Pr);           pi = __ldg(Pr + HID);
            pg = __ldg(Pr + 2 * HID); po = __ldg(Pr + 3 * HID);
        }
        __syncthreads();   // h_t now globally visible (transitively via warp1's acquire)

        // load this lane's 32 h values straight from L2 into packed f32x2 regs
        ull hp2[16];
        {
            const float* hb = g_H + (size_t)t * HID + khalf * 1024 + lane * 8;
#pragma unroll
            for (int c = 0; c < 4; c++) {
                float4 a = __ldcg((const float4*)(hb + c * 256));
                float4 d = __ldcg((const float4*)(hb + c * 256 + 4));
                hp2[c * 4 + 0] = packf2(a.x, a.y);
                hp2[c * 4 + 1] = packf2(a.z, a.w);
                hp2[c * 4 + 2] = packf2(d.x, d.y);
                hp2[c * 4 + 3] = packf2(d.z, d.w);
            }
        }

        // per-row scalar partials
        float s[7];
#pragma unroll
        for (int j = 0; j < 7; j++) s[j] = 0.0f;

        for (int j = 0; j < nrows; j++) {
            int gr = wslot + 8 * j;
            const uint4* wp = wsm + gr * 256 + khalf * 128 + lane;
            uint4 w0 = wp[0], w1 = wp[32], w2 = wp[64], w3 = wp[96];
            ull a0 = 0ull, a1 = 0ull, a2 = 0ull, a3 = 0ull;
            ffma2(a0, packf2(bflo(w0.x), bfhi(w0.x)), hp2[0]);
            ffma2(a1, packf2(bflo(w0.y), bfhi(w0.y)), hp2[1]);
            ffma2(a2, packf2(bflo(w0.z), bfhi(w0.z)), hp2[2]);
            ffma2(a3, packf2(bflo(w0.w), bfhi(w0.w)), hp2[3]);
            ffma2(a0, packf2(bflo(w1.x), bfhi(w1.x)), hp2[4]);
            ffma2(a1, packf2(bflo(w1.y), bfhi(w1.y)), hp2[5]);
            ffma2(a2, packf2(bflo(w1.z), bfhi(w1.z)), hp2[6]);
            ffma2(a3, packf2(bflo(w1.w), bfhi(w1.w)), hp2[7]);
            ffma2(a0, packf2(bflo(w2.x), bfhi(w2.x)), hp2[8]);
            ffma2(a1, packf2(bflo(w2.y), bfhi(w2.y)), hp2[9]);
            ffma2(a2, packf2(bflo(w2.z), bfhi(w2.z)), hp2[10]);
            ffma2(a3, packf2(bflo(w2.w), bfhi(w2.w)), hp2[11]);
            ffma2(a0, packf2(bflo(w3.x), bfhi(w3.x)), hp2[12]);
            ffma2(a1, packf2(bflo(w3.y), bfhi(w3.y)), hp2[13]);
            ffma2(a2, packf2(bflo(w3.z), bfhi(w3.z)), hp2[14]);
            ffma2(a3, packf2(bflo(w3.w), bfhi(w3.w)), hp2[15]);
            float l0, h0, l1, h1, l2, h2, l3, h3;
            unpackf2(a0, l0, h0); unpackf2(a1, l1, h1);
            unpackf2(a2, l2, h2); unpackf2(a3, l3, h3);
            s[j] = ((l0 + h0) + (l1 + h1)) + ((l2 + h2) + (l3 + h3));
        }

        // batched interleaved shuffle reduction
#pragma unroll
        for (int off = 16; off > 0; off >>= 1) {
#pragma unroll
            for (int j = 0; j < 7; j++)
                s[j] += __shfl_xor_sync(0xffffffffu, s[j], off);
        }
        if (lane == 0)
            for (int j = 0; j < nrows; j++)
                gacc[(wslot + 8 * j) * 2 + khalf] = s[j];
        __syncthreads();

        // epilogue: warp 0 only (R <= 14 < 32); publish h_{t+1} + flag
        if (warp == 0) {
            if (lane < R) {
                float fg = sigmoid_f(gacc[(4 * lane + 0) * 2] + gacc[(4 * lane + 0) * 2 + 1] + pf);
                float ig = sigmoid_f(gacc[(4 * lane + 1) * 2] + gacc[(4 * lane + 1) * 2 + 1] + pi);
                float gg = tanh_f   (gacc[(4 * lane + 2) * 2] + gacc[(4 * lane + 2) * 2 + 1] + pg);
                float og = sigmoid_f(gacc[(4 * lane + 3) * 2] + gacc[(4 * lane + 3) * 2 + 1] + po);
                cst = fg * cst + ig * gg;
                float hn = og * tanh_f(cst);
                g_H[(size_t)(t + 1) * HID + rbase + lane] = hn;
                if (t == SEQ_LEN - 1) {
                    dout[(size_t)SEQ_LEN * NCH + rbase + lane] = hn;
                    dout[(size_t)SEQ_LEN * NCH + HID + rbase + lane] = cst;
                }
            }
            __syncwarp();
            if (lane == 0) st_flag_release(&g_flags[b], (unsigned)(t + 2));
        }
    }
}

// ---- FC: out[t][c] = bfc[c] + Wfc[c] . h_{t+1} ----
__global__ void __launch_bounds__(256) fc_kernel(
    const float* __restrict__ Wfc, const float* __restrict__ bfc,
    float* __restrict__ out)
{
    __shared__ float sH[128 * 33];
    __shared__ float sW[128 * 33];
    const int tid = threadIdx.x;
    const int ty = tid >> 4, tx = tid & 15;
    const int tb = blockIdx.x * 128;

    float acc[8][8];
#pragma unroll
    for (int i = 0; i < 8; i++)
#pragma unroll
        for (int j = 0; j < 8; j++) acc[i][j] = 0.0f;

    for (int kb = 0; kb < 64; kb++) {
        __syncthreads();
        for (int i = tid; i < 128 * 32; i += 256) {
            int r = i >> 5, k = i & 31;
            sH[r * 33 + k] = g_H[(size_t)(tb + r + 1) * HID + kb * 32 + k];
            sW[r * 33 + k] = Wfc[(size_t)r * HID + kb * 32 + k];
        }
        __syncthreads();
        for (int k = 0; k < 32; k++) {
            float hv[8], wv[8];
#pragma unroll
            for (int i = 0; i < 8; i++) hv[i] = sH[(ty + 16 * i) * 33 + k];
#pragma unroll
            for (int j = 0; j < 8; j++) wv[j] = sW[(tx + 16 * j) * 33 + k];
#pragma unroll
            for (int i = 0; i < 8; i++)
#pragma unroll
                for (int j = 0; j < 8; j++) acc[i][j] = fmaf(hv[i], wv[j], acc[i][j]);
        }
    }
#pragma unroll
    for (int i = 0; i < 8; i++)
#pragma unroll
        for (int j = 0; j < 8; j++)
            out[(size_t)(tb + ty + 16 * i) * NCH + tx + 16 * j] = acc[i][j] + bfc[tx + 16 * j];
}

extern "C" void kernel_launch(void* const* d_in, const int* in_sizes, int n_in,
                              void* d_out, int out_size)
{
    const int*   seq = (const int*)  d_in[0];
    const float* emb = (const float*)d_in[1];
    const float* Wf  = (const float*)d_in[2];
    const float* bf  = (const float*)d_in[3];
    const float* Wi  = (const float*)d_in[4];
    const float* bi  = (const float*)d_in[5];
    const float* Wg  = (const float*)d_in[6];
    const float* bg  = (const float*)d_in[7];
    const float* Wo  = (const float*)d_in[8];
    const float* bo  = (const float*)d_in[9];
    const float* Wfc = (const float*)d_in[10];
    const float* bfc = (const float*)d_in[11];
    float* out = (float*)d_out;

    cudaFuncSetAttribute(lstm_persist, cudaFuncAttributeMaxDynamicSharedMemorySize, LSTM_SMEM);
    cudaFuncSetAttribute(pgemm_kernel, cudaFuncAttributeMaxDynamicSharedMemorySize, PGEMM_SMEM);

    int dev = 0, nsm = 0;
    cudaGetDevice(&dev);
    cudaDeviceGetAttribute(&nsm, cudaDevAttrMultiProcessorCount, dev);
    if (nsm <= 0 || nsm > 160) nsm = 148;

    init_flags<<<1, NFLAGS>>>(nsm);
    wh_convert<<<(int)(((size_t)4 * HID * HID / 2 + 255) / 256), 256>>>(Wf, Wi, Wg, Wo);
    pgemm_kernel<<<128, 256, PGEMM_SMEM>>>(Wf, bf, Wi, bi, Wg, bg, Wo, bo, emb);
    lstm_persist<<<nsm, 512, LSTM_SMEM>>>(seq, out);
    fc_kernel<<<SEQ_LEN / 128, 256>>>(Wfc, bfc, out);
}

// round 17
// speedup vs baseline: 2.7492x; 2.7492x over previous
#include <cuda_runtime.h>
#include <cuda_bf16.h>
#include <cstdint>
#include <cstddef>

#define SEQ_LEN 16384
#define HID 2048
#define EMBD 512
#define NCH 128
#define ZD 2560
#define SMEM_ROWS 54
#define LSTM_SMEM (SMEM_ROWS * 4096 + HID * 4 + 128 * 4)  // 229,888 B (<= 232,448 opt-in)
#define PGEMM_SMEM ((64 + 128) * 129 * 4)                 // 99,072 B
#define MAGIC 0xFF800001u                                  // NaN pattern; never produced by LSTM

typedef unsigned long long ull;

__device__ __nv_bfloat16 g_Wh[(size_t)4 * HID * HID];      // [gate][row][k], k over h-part
__device__ float         g_P[(size_t)NCH * 4 * HID];       // x-part preact + bias
__device__ float         g_H[((size_t)SEQ_LEN + 1) * HID]; // h history (self-flagging via MAGIC)

__device__ __forceinline__ float bflo(unsigned int w) { return __uint_as_float(w << 16); }
__device__ __forceinline__ float bfhi(unsigned int w) { return __uint_as_float(w & 0xffff0000u); }
__device__ __forceinline__ float sigmoid_f(float x) { return 1.0f / (1.0f + __expf(-x)); }
__device__ __forceinline__ float tanh_f(float x)    { return 2.0f / (1.0f + __expf(-2.0f * x)) - 1.0f; }

__device__ __forceinline__ ull packf2(float lo, float hi) {
    ull r; asm("mov.b64 %0, {%1, %2};" : "=l"(r) : "f"(lo), "f"(hi)); return r;
}
__device__ __forceinline__ void unpackf2(ull v, float& lo, float& hi) {
    asm("mov.b64 {%0, %1}, %2;" : "=f"(lo), "=f"(hi) : "l"(v));
}
__device__ __forceinline__ void ffma2(ull& d, ull a, ull b) {
    asm("fma.rn.f32x2 %0, %1, %2, %0;" : "+l"(d) : "l"(a), "l"(b));
}

// ---- poison h history with MAGIC so data itself signals readiness ----
__global__ void __launch_bounds__(256) poison_H() {
    size_t i = (size_t)blockIdx.x * 256 + threadIdx.x;
    size_t n = (size_t)(SEQ_LEN + 1) * HID / 4;
    if (i < n) {
        uint4 m; m.x = MAGIC; m.y = MAGIC; m.z = MAGIC; m.w = MAGIC;
        reinterpret_cast<uint4*>(g_H)[i] = m;
    }
}

// ---- convert recurrent halves of Wf/Wi/Wg/Wo to bf16 ----
__global__ void __launch_bounds__(256) wh_convert(
    const float* __restrict__ Wf, const float* __restrict__ Wi,
    const float* __restrict__ Wg, const float* __restrict__ Wo)
{
    size_t idx = (size_t)blockIdx.x * 256 + threadIdx.x;   // bf16-pair index
    if (idx >= (size_t)4 * HID * HID / 2) return;
    unsigned gate = (unsigned)(idx >> 21);
    unsigned rem  = (unsigned)idx & ((1u << 21) - 1u);
    unsigned row  = rem >> 10;
    unsigned p    = rem & 1023u;
    const float* W = (gate == 0) ? Wf : (gate == 1) ? Wi : (gate == 2) ? Wg : Wo;
    float2 v = *(const float2*)(W + (size_t)row * ZD + EMBD + 2u * p);
    reinterpret_cast<__nv_bfloat162*>(g_Wh)[idx] = __floats2bfloat162_rn(v.x, v.y);
}

// ---- P table: [8192 x 512] @ [512 x 128] exact fp32 ----
__global__ void __launch_bounds__(256) pgemm_kernel(
    const float* __restrict__ Wf, const float* __restrict__ bf,
    const float* __restrict__ Wi, const float* __restrict__ bi,
    const float* __restrict__ Wg, const float* __restrict__ bg,
    const float* __restrict__ Wo, const float* __restrict__ bo,
    const float* __restrict__ emb)
{
    extern __shared__ float psm[];
    float* sW = psm;               // [64][129]
    float* sE = psm + 64 * 129;    // [128][129]
    const int tid = threadIdx.x;
    const int ty = tid >> 4, tx = tid & 15;
    const int gpos0 = blockIdx.x * 64;
    const int gate = gpos0 >> 11;
    const int rowbase = gpos0 & (HID - 1);
    const float* W  = (gate == 0) ? Wf : (gate == 1) ? Wi : (gate == 2) ? Wg : Wo;
    const float* bb = (gate == 0) ? bf : (gate == 1) ? bi : (gate == 2) ? bg : bo;

    float acc[4][8];
#pragma unroll
    for (int i = 0; i < 4; i++)
#pragma unroll
        for (int j = 0; j < 8; j++) acc[i][j] = 0.0f;

    for (int kb = 0; kb < 4; kb++) {
        __syncthreads();
        for (int i = tid; i < 64 * 128; i += 256) {
            int r = i >> 7, k = i & 127;
            sW[r * 129 + k] = W[(size_t)(rowbase + r) * ZD + kb * 128 + k];
        }
        for (int i = tid; i < 128 * 128; i += 256) {
            int c = i >> 7, k = i & 127;
            sE[c * 129 + k] = emb[(size_t)c * EMBD + kb * 128 + k];
        }
        __syncthreads();
        for (int k = 0; k < 128; k++) {
            float wv[4], ev[8];
#pragma unroll
            for (int i = 0; i < 4; i++) wv[i] = sW[(ty + 16 * i) * 129 + k];
#pragma unroll
            for (int j = 0; j < 8; j++) ev[j] = sE[(tx + 16 * j) * 129 + k];
#pragma unroll
            for (int i = 0; i < 4; i++)
#pragma unroll
                for (int j = 0; j < 8; j++) acc[i][j] = fmaf(wv[i], ev[j], acc[i][j]);
        }
    }
#pragma unroll
    for (int i = 0; i < 4; i++) {
        float bv = bb[rowbase + ty + 16 * i];
#pragma unroll
        for (int j = 0; j < 8; j++)
            g_P[(size_t)(tx + 16 * j) * (4 * HID) + gpos0 + ty + 16 * i] = acc[i][j] + bv;
    }
}

// ---- persistent LSTM: data-polling sync (no barrier, no flags) ----
__global__ void __launch_bounds__(512, 1) lstm_persist(
    const int* __restrict__ seq, float* __restrict__ dout)
{
    const int nb = gridDim.x, b = blockIdx.x;
    const int qq = HID / nb, rm = HID % nb;
    const int R = qq + (b < rm ? 1 : 0);
    const int rbase = b * qq + (b < rm ? b : rm);
    const int nGR = 4 * R;
    const int nSm = (nGR < SMEM_ROWS) ? nGR : SMEM_ROWS;
    const int tid = threadIdx.x, warp = tid >> 5, lane = tid & 31;
    const int khalf = warp & 1;        // 1024-wide half of the dot
    const int wslot = warp >> 1;       // 0..7 : row slot
    const int nrows = (nGR > wslot) ? ((nGR - wslot + 7) >> 3) : 0;  // 6 or 7

    extern __shared__ unsigned char smraw[];
    uint4* wsm  = (uint4*)smraw;                                   // [SMEM_ROWS][256]
    float* hsm  = (float*)(smraw + SMEM_ROWS * 4096);              // [2048]
    float* gacc = (float*)(smraw + SMEM_ROWS * 4096 + HID * 4);    // [56][2]

    // publish h_0 = 0 immediately (unblocks other blocks' t=0 polls)
    if (warp == 0 && lane < R) __stcg(&g_H[rbase + lane], 0.0f);

    // prologue: resident weight rows into SMEM
    for (int gr = 0; gr < nSm; gr++) {
        int gate = gr & 3, row = rbase + (gr >> 2);
        const uint4* src = (const uint4*)(g_Wh + ((size_t)gate * HID + row) * HID);
        if (tid < 256) wsm[gr * 256 + tid] = __ldg(src + tid);
    }
    // at most one overflow gate-row per wslot, held in registers forever
    int grL2 = -1;
    for (int gr = wslot; gr < nGR; gr += 8) if (gr >= nSm) grL2 = gr;
    uint4 pre0 = {0,0,0,0}, pre1 = {0,0,0,0}, pre2 = {0,0,0,0}, pre3 = {0,0,0,0};
    if (grL2 >= 0) {
        int gate = grL2 & 3, row = rbase + (grL2 >> 2);
        const uint4* wp = (const uint4*)(g_Wh + ((size_t)gate * HID + row) * HID)
                          + khalf * 128 + lane;
        pre0 = __ldg(wp); pre1 = __ldg(wp + 32); pre2 = __ldg(wp + 64); pre3 = __ldg(wp + 96);
    }
    float cst = 0.0f;
    __syncthreads();

    for (int t = 0; t < SEQ_LEN; t++) {
        // warp 0: prefetch x-part preactivations (independent of h_t)
        float pf = 0.f, pi = 0.f, pg = 0.f, po = 0.f;
        if (warp == 0 && lane < R) {
            int ch = __ldg(seq + t);
            const float* Pr = g_P + (size_t)ch * (4 * HID) + rbase + lane;
            pf = __ldg(Pr);           pi = __ldg(Pr + HID);
            pg = __ldg(Pr + 2 * HID); po = __ldg(Pr + 3 * HID);
        }

        // each thread polls ITS 16B of h_t directly from L2, stages to SMEM
        {
            const float4* src = ((const float4*)(g_H + (size_t)t * HID)) + tid;
            float4 hv;
            for (;;) {
                asm volatile("ld.global.cg.v4.f32 {%0,%1,%2,%3}, [%4];"
                    : "=f"(hv.x), "=f"(hv.y), "=f"(hv.z), "=f"(hv.w) : "l"(src));
                bool bad = (__float_as_uint(hv.x) == MAGIC) | (__float_as_uint(hv.y) == MAGIC) |
                           (__float_as_uint(hv.z) == MAGIC) | (__float_as_uint(hv.w) == MAGIC);
                if (!bad) break;
                __nanosleep(30);
            }
            ((float4*)hsm)[tid] = hv;
        }
        __syncthreads();

        // cache this lane's 32 h values as 16 packed f32x2 pairs
        ull hp2[16];
        {
            const float* hb = hsm + khalf * 1024 + lane * 8;
#pragma unroll
            for (int c = 0; c < 4; c++) {
                float4 a = *(const float4*)(hb + c * 256);
                float4 d = *(const float4*)(hb + c * 256 + 4);
                hp2[c * 4 + 0] = packf2(a.x, a.y);
                hp2[c * 4 + 1] = packf2(a.z, a.w);
                hp2[c * 4 + 2] = packf2(d.x, d.y);
                hp2[c * 4 + 3] = packf2(d.z, d.w);
            }
        }

        float s[7];
#pragma unroll
        for (int j = 0; j < 7; j++) s[j] = 0.0f;

        for (int j = 0; j < nrows; j++) {
            int gr = wslot + 8 * j;
            uint4 w0, w1, w2, w3;
            if (gr < nSm) {
                const uint4* wp = wsm + gr * 256 + khalf * 128 + lane;
                w0 = wp[0]; w1 = wp[32]; w2 = wp[64]; w3 = wp[96];
            } else {
                w0 = pre0; w1 = pre1; w2 = pre2; w3 = pre3;
            }
            ull a0 = 0ull, a1 = 0ull, a2 = 0ull, a3 = 0ull;
            ffma2(a0, packf2(bflo(w0.x), bfhi(w0.x)), hp2[0]);
            ffma2(a1, packf2(bflo(w0.y), bfhi(w0.y)), hp2[1]);
            ffma2(a2, packf2(bflo(w0.z), bfhi(w0.z)), hp2[2]);
            ffma2(a3, packf2(bflo(w0.w), bfhi(w0.w)), hp2[3]);
            ffma2(a0, packf2(bflo(w1.x), bfhi(w1.x)), hp2[4]);
            ffma2(a1, packf2(bflo(w1.y), bfhi(w1.y)), hp2[5]);
            ffma2(a2, packf2(bflo(w1.z), bfhi(w1.z)), hp2[6]);
            ffma2(a3, packf2(bflo(w1.w), bfhi(w1.w)), hp2[7]);
            ffma2(a0, packf2(bflo(w2.x), bfhi(w2.x)), hp2[8]);
            ffma2(a1, packf2(bflo(w2.y), bfhi(w2.y)), hp2[9]);
            ffma2(a2, packf2(bflo(w2.z), bfhi(w2.z)), hp2[10]);
            ffma2(a3, packf2(bflo(w2.w), bfhi(w2.w)), hp2[11]);
            ffma2(a0, packf2(bflo(w3.x), bfhi(w3.x)), hp2[12]);
            ffma2(a1, packf2(bflo(w3.y), bfhi(w3.y)), hp2[13]);
            ffma2(a2, packf2(bflo(w3.z), bfhi(w3.z)), hp2[14]);
            ffma2(a3, packf2(bflo(w3.w), bfhi(w3.w)), hp2[15]);
            float l0, h0, l1, h1, l2, h2, l3, h3;
            unpackf2(a0, l0, h0); unpackf2(a1, l1, h1);
            unpackf2(a2, l2, h2); unpackf2(a3, l3, h3);
            s[j] = ((l0 + h0) + (l1 + h1)) + ((l2 + h2) + (l3 + h3));
        }

        // batched interleaved shuffle reduction
#pragma unroll
        for (int off = 16; off > 0; off >>= 1) {
#pragma unroll
            for (int j = 0; j < 7; j++)
                s[j] += __shfl_xor_sync(0xffffffffu, s[j], off);
        }
        if (lane == 0)
            for (int j = 0; j < nrows; j++)
                gacc[(wslot + 8 * j) * 2 + khalf] = s[j];
        __syncthreads();

        // epilogue: warp 0 computes gates, publishes h_{t+1} (data IS the flag)
        if (warp == 0 && lane < R) {
            float fg = sigmoid_f(gacc[(4 * lane + 0) * 2] + gacc[(4 * lane + 0) * 2 + 1] + pf);
            float ig = sigmoid_f(gacc[(4 * lane + 1) * 2] + gacc[(4 * lane + 1) * 2 + 1] + pi);
            float gg = tanh_f   (gacc[(4 * lane + 2) * 2] + gacc[(4 * lane + 2) * 2 + 1] + pg);
            float og = sigmoid_f(gacc[(4 * lane + 3) * 2] + gacc[(4 * lane + 3) * 2 + 1] + po);
            cst = fg * cst + ig * gg;
            float hn = og * tanh_f(cst);
            __stcg(&g_H[(size_t)(t + 1) * HID + rbase + lane], hn);
            if (t == SEQ_LEN - 1) {
                dout[(size_t)SEQ_LEN * NCH + rbase + lane] = hn;
                dout[(size_t)SEQ_LEN * NCH + HID + rbase + lane] = cst;
            }
        }
        // no trailing barrier: next iteration's poll waits on data itself
    }
}

// ---- FC: out[t][c] = bfc[c] + Wfc[c] . h_{t+1} ----
__global__ void __launch_bounds__(256) fc_kernel(
    const float* __restrict__ Wfc, const float* __restrict__ bfc,
    float* __restrict__ out)
{
    __shared__ float sH[128 * 33];
    __shared__ float sW[128 * 33];
    const int tid = threadIdx.x;
    const int ty = tid >> 4, tx = tid & 15;
    const int tb = blockIdx.x * 128;

    float acc[8][8];
#pragma unroll
    for (int i = 0; i < 8; i++)
#pragma unroll
        for (int j = 0; j < 8; j++) acc[i][j] = 0.0f;

    for (int kb = 0; kb < 64; kb++) {
        __syncthreads();
        for (int i = tid; i < 128 * 32; i += 256) {
            int r = i >> 5, k = i & 31;
            sH[r * 33 + k] = g_H[(size_t)(tb + r + 1) * HID + kb * 32 + k];
            sW[r * 33 + k] = Wfc[(size_t)r * HID + kb * 32 + k];
        }
        __syncthreads();
        for (int k = 0; k < 32; k++) {
            float hv[8], wv[8];
#pragma unroll
            for (int i = 0; i < 8; i++) hv[i] = sH[(ty + 16 * i) * 33 + k];
#pragma unroll
            for (int j = 0; j < 8; j++) wv[j] = sW[(tx + 16 * j) * 33 + k];
#pragma unroll
            for (int i = 0; i < 8; i++)
#pragma unroll
                for (int j = 0; j < 8; j++) acc[i][j] = fmaf(hv[i], wv[j], acc[i][j]);
        }
    }
#pragma unroll
    for (int i = 0; i < 8; i++)
#pragma unroll
        for (int j = 0; j < 8; j++)
            out[(size_t)(tb + ty + 16 * i) * NCH + tx + 16 * j] = acc[i][j] + bfc[tx + 16 * j];
}

extern "C" void kernel_launch(void* const* d_in, const int* in_sizes, int n_in,
                              void* d_out, int out_size)
{
    const int*   seq = (const int*)  d_in[0];
    const float* emb = (const float*)d_in[1];
    const float* Wf  = (const float*)d_in[2];
    const float* bf  = (const float*)d_in[3];
    const float* Wi  = (const float*)d_in[4];
    const float* bi  = (const float*)d_in[5];
    const float* Wg  = (const float*)d_in[6];
    const float* bg  = (const float*)d_in[7];
    const float* Wo  = (const float*)d_in[8];
    const float* bo  = (const float*)d_in[9];
    const float* Wfc = (const float*)d_in[10];
    const float* bfc = (const float*)d_in[11];
    float* out = (float*)d_out;

    cudaFuncSetAttribute(lstm_persist, cudaFuncAttributeMaxDynamicSharedMemorySize, LSTM_SMEM);
    cudaFuncSetAttribute(pgemm_kernel, cudaFuncAttributeMaxDynamicSharedMemorySize, PGEMM_SMEM);

    int dev = 0, nsm = 0;
    cudaGetDevice(&dev);
    cudaDeviceGetAttribute(&nsm, cudaDevAttrMultiProcessorCount, dev);
    if (nsm <= 0 || nsm > 160) nsm = 148;

    size_t nPoison4 = (size_t)(SEQ_LEN + 1) * HID / 4;
    poison_H<<<(int)((nPoison4 + 255) / 256), 256>>>();
    wh_convert<<<(int)(((size_t)4 * HID * HID / 2 + 255) / 256), 256>>>(Wf, Wi, Wg, Wo);
    pgemm_kernel<<<128, 256, PGEMM_SMEM>>>(Wf, bf, Wi, bi, Wg, bg, Wo, bo, emb);
    lstm_persist<<<nsm, 512, LSTM_SMEM>>>(seq, out);
    fc_kernel<<<SEQ_LEN / 128, 256>>>(Wfc, bfc, out);
}